// round 4
// baseline (speedup 1.0000x reference)
#include <cuda_runtime.h>
#include <math.h>

#define PS 16
#define PH 64
#define PW 64
#define NPATCH (PH*PW)
#define NB 32
#define IH 1024
#define IW 1024
#define ROWF4 (IW/4)
#define BANDS 4
#define BPH (PH/BANDS)          // 16 patch-rows per band

// Scratch (no device allocation allowed)
__device__ float g_qual [NB*NPATCH];
__device__ float g_pmean[NB*NPATCH];
__device__ int   g_code [NPATCH];
__device__ float g_scale[NPATCH];
__device__ float g_mpp  [NPATCH];

// ---------------------------------------------------------------------------
// Kernel 1: per-(batch, patch) quality + mean for one band. float4 loads.
// Default caching so the band (32 MB) stays L2-resident for apply.
// ---------------------------------------------------------------------------
__global__ void stats_kernel(const float4* __restrict__ img, int sy0) {
    const int tx = threadIdx.x;
    const int sy = sy0 + blockIdx.x;     // patch row
    const int b  = blockIdx.y;

    const float4* base = img + ((size_t)b * IH + (size_t)sy * PS) * ROWF4 + tx;

    float s = 0.f, ss = 0.f;
#pragma unroll
    for (int y = 0; y < PS; ++y) {
        float4 v = base[(size_t)y * ROWF4];
        s  += (v.x + v.y) + (v.z + v.w);
        ss  = fmaf(v.x, v.x, ss);
        ss  = fmaf(v.y, v.y, ss);
        ss  = fmaf(v.z, v.z, ss);
        ss  = fmaf(v.w, v.w, ss);
    }
#pragma unroll
    for (int off = 2; off >= 1; off >>= 1) {
        s  += __shfl_down_sync(0xffffffffu, s,  off, 4);
        ss += __shfl_down_sync(0xffffffffu, ss, off, 4);
    }
    if ((tx & 3) == 0) {
        float mean = s * (1.0f / 256.0f);
        float var  = (ss - s * s * (1.0f / 256.0f)) * (1.0f / 255.0f); // ddof=1
        var = fmaxf(var, 0.0f);
        float std_ = sqrtf(var);
        float iq   = 1.0f - 2.0f * fabsf(mean - 0.5f);
        float quality = (std_ + iq + var) * (1.0f / 3.0f);
        int p = sy * PW + (tx >> 2);
        g_qual [b * NPATCH + p] = quality;
        g_pmean[b * NPATCH + p] = mean;
    }
}

// ---------------------------------------------------------------------------
// Kernel 2: per-patch code/scale/mpp for one band. Deterministic reduction.
// ---------------------------------------------------------------------------
__global__ void code_kernel(const float* __restrict__ r_strong,
                            const float* __restrict__ r_drop,
                            const float* __restrict__ r_else,
                            const float* __restrict__ bright_f,
                            const float* __restrict__ contrast_f,
                            const float* __restrict__ slight_f,
                            const int*   __restrict__ aug_choice,
                            const int*   __restrict__ slight_choice,
                            int p0) {
    int p = p0 + blockIdx.x * 256 + threadIdx.x;

    float q = 0.f, m = 0.f;
#pragma unroll
    for (int b = 0; b < NB; ++b) {
        q += g_qual [b * NPATCH + p];
        m += g_pmean[b * NPATCH + p];
    }
    q *= (1.0f / NB);
    m *= (1.0f / NB);

    bool low    = q < 0.7f;
    bool strong = low  && (r_strong[p] < 0.8f);
    bool drop   = low  && (q < 0.3f) && (r_drop[p] < 0.1f);
    bool els    = !low && (r_else[p] < 0.3f);

    int code = 0;
    if (strong) code = aug_choice[p] + 1;      // 1..4
    if (els)    code = slight_choice[p] + 5;   // 5..6
    if (drop)   code = 7;

    float scale = 0.f;
    if      (code == 1) scale = 0.1f;
    else if (code == 3) scale = bright_f[p];
    else if (code == 4) scale = contrast_f[p];
    else if (code == 5) scale = 0.05f;
    else if (code == 6) scale = slight_f[p];

    g_code [p] = code;
    g_scale[p] = scale;
    g_mpp  [p] = m;
}

__device__ __forceinline__ float clamp01(float x) {
    return fminf(fmaxf(x, 0.0f), 1.0f);
}

// ---------------------------------------------------------------------------
// Kernel 3: apply (one band). Single pass, register-resident, no smem.
// Thread owns one column of a 16x256 strip: 16 front-batched loads (should
// hit L2 on the band stats just read), compute, 16 streaming stores.
// Blur: vertical neighbors in registers, horizontal via 16-wide shfl.
// ---------------------------------------------------------------------------
__global__ void apply_kernel(const float* __restrict__ img,
                             const float* __restrict__ noise,
                             float* __restrict__ out,
                             int sy0) {
    const int tx = threadIdx.x;
    const int x  = blockIdx.x * 256 + tx;
    const int sy = sy0 + blockIdx.y;
    const int b  = blockIdx.z;

    const size_t base = ((size_t)b * IH + (size_t)sy * PS) * IW + x;

    // Front-batched loads: 16 independent LDGs -> high MLP, L2-hot.
    float v[PS];
#pragma unroll
    for (int y = 0; y < PS; ++y)
        v[y] = img[base + (size_t)y * IW];

    const int   p     = sy * PW + (x >> 4);
    const int   code  = g_code[p];
    const float scale = g_scale[p];
    const float mpp   = g_mpp[p];
    const int   lx    = tx & 15;
    const unsigned gmask = 0xFFFFu << (tx & 16);

    float r[PS];
    if (code == 0) {
#pragma unroll
        for (int y = 0; y < PS; ++y) r[y] = v[y];
    } else if (code == 7) {
#pragma unroll
        for (int y = 0; y < PS; ++y) r[y] = 0.0f;
    } else if (code == 2) {
        float hs[PS];
#pragma unroll
        for (int y = 0; y < PS; ++y) {
            float l  = __shfl_up_sync  (gmask, v[y], 1, 16);
            float rr = __shfl_down_sync(gmask, v[y], 1, 16);
            if (lx == 0)  l  = 0.0f;
            if (lx == 15) rr = 0.0f;
            hs[y] = v[y] + l + rr;
        }
#pragma unroll
        for (int y = 0; y < PS; ++y) {
            float sum = hs[y];
            if (y > 0)      sum += hs[y - 1];
            if (y < PS - 1) sum += hs[y + 1];
            r[y] = sum * (1.0f / 9.0f);
        }
    } else if (code == 1 || code == 5) {
        float n[PS];
#pragma unroll
        for (int y = 0; y < PS; ++y)
            n[y] = noise[base + (size_t)y * IW];
#pragma unroll
        for (int y = 0; y < PS; ++y)
            r[y] = clamp01(fmaf(n[y], scale, v[y]));
    } else if (code == 3 || code == 6) {
#pragma unroll
        for (int y = 0; y < PS; ++y)
            r[y] = clamp01(v[y] * scale);
    } else { // code == 4 (contrast)
#pragma unroll
        for (int y = 0; y < PS; ++y)
            r[y] = clamp01(fmaf(v[y] - mpp, scale, mpp));
    }

    // Streaming stores: evict-first, minimize L2 pollution of the img band.
#pragma unroll
    for (int y = 0; y < PS; ++y)
        __stcs(&out[base + (size_t)y * IW], r[y]);
}

extern "C" void kernel_launch(void* const* d_in, const int* in_sizes, int n_in,
                              void* d_out, int out_size) {
    const float4* img4         = (const float4*)d_in[0];
    const float* img           = (const float*)d_in[0];
    const float* noise         = (const float*)d_in[1];
    const float* r_strong      = (const float*)d_in[2];
    const float* r_drop        = (const float*)d_in[3];
    const float* r_else        = (const float*)d_in[4];
    const float* bright_f      = (const float*)d_in[5];
    const float* contrast_f    = (const float*)d_in[6];
    const float* slight_f      = (const float*)d_in[7];
    const int*   aug_choice    = (const int*)d_in[8];
    const int*   slight_choice = (const int*)d_in[9];
    float* out = (float*)d_out;

    for (int band = 0; band < BANDS; ++band) {
        const int sy0 = band * BPH;
        stats_kernel<<<dim3(BPH, NB), 256>>>(img4, sy0);
        code_kernel<<<(BPH * PW) / 256, 256>>>(r_strong, r_drop, r_else,
                                               bright_f, contrast_f, slight_f,
                                               aug_choice, slight_choice,
                                               sy0 * PW);
        apply_kernel<<<dim3(IW / 256, BPH, NB), 256>>>(img, noise, out, sy0);
    }
}

// round 5
// speedup vs baseline: 1.5017x; 1.5017x over previous
#include <cuda_runtime.h>
#include <math.h>

#define PS 16
#define PH 64
#define PW 64
#define NPATCH (PH*PW)
#define NB 32
#define IH 1024
#define IW 1024
#define IMGSZ (IH*IW)           // floats per image
#define TROW 17                 // padded tile row stride (bank-conflict break)
#define TBATCH (PS*TROW)        // 272 floats per batch slice

__device__ __forceinline__ float clamp01(float x) {
    return fminf(fmaxf(x, 0.0f), 1.0f);
}

// ---------------------------------------------------------------------------
// One CTA = one patch position (sy,px), all 32 batches. 256 threads.
// Thread t owns pixel (r=t>>4, c=t&15) of the patch in every batch.
//  Phase 1: 32 coalesced loads -> v[32] regs + smem tile (transpose).
//  Phase 2: stats: thread (b=t>>3, j=t&7) sums rows 2j,2j+1 of batch b from
//           the tile, width-8 shfl reduce -> per-b quality/mean.
//  Phase 3: thread 0 reduces over b, computes code/scale/mpp (in-CTA).
//  Phase 4: apply (CTA-uniform branch) from regs; blur from tile.
// ---------------------------------------------------------------------------
__global__ void __launch_bounds__(256, 3)
fused_kernel(const float* __restrict__ img,
             const float* __restrict__ noise,
             const float* __restrict__ r_strong,
             const float* __restrict__ r_drop,
             const float* __restrict__ r_else,
             const float* __restrict__ bright_f,
             const float* __restrict__ contrast_f,
             const float* __restrict__ slight_f,
             const int*   __restrict__ aug_choice,
             const int*   __restrict__ slight_choice,
             float* __restrict__ out) {
    __shared__ float tile[NB * TBATCH];       // 34.8 KB staged patch data
    __shared__ float s_qual[NB];
    __shared__ float s_mean[NB];
    __shared__ int   s_code;
    __shared__ float s_scale;
    __shared__ float s_mpp;

    const int p  = blockIdx.x;                // patch index 0..4095
    const int sy = p >> 6;
    const int px = p & 63;
    const int t  = threadIdx.x;
    const int r  = t >> 4;
    const int c  = t & 15;

    const size_t pbase = ((size_t)(sy * PS + r)) * IW + px * PS + c;

    // ---- Phase 1: load all batches (coalesced 64B segments), stage tile ----
    float v[NB];
#pragma unroll
    for (int b = 0; b < NB; ++b)
        v[b] = img[pbase + (size_t)b * IMGSZ];
#pragma unroll
    for (int b = 0; b < NB; ++b)
        tile[b * TBATCH + r * TROW + c] = v[b];
    __syncthreads();

    // ---- Phase 2: per-(b,patch) stats ----
    {
        const int bb = t >> 3;                // batch this thread reduces
        const int j  = t & 7;                 // row-pair 2j, 2j+1
        const float* trow = tile + bb * TBATCH + (2 * j) * TROW;
        float s = 0.f, ss = 0.f;
#pragma unroll
        for (int k = 0; k < 2; ++k) {
#pragma unroll
            for (int cc = 0; cc < PS; ++cc) {
                float x = trow[k * TROW + cc];
                s  += x;
                ss  = fmaf(x, x, ss);
            }
        }
#pragma unroll
        for (int off = 4; off >= 1; off >>= 1) {
            s  += __shfl_down_sync(0xffffffffu, s,  off, 8);
            ss += __shfl_down_sync(0xffffffffu, ss, off, 8);
        }
        if (j == 0) {
            float mean = s * (1.0f / 256.0f);
            float var  = (ss - s * s * (1.0f / 256.0f)) * (1.0f / 255.0f); // ddof=1
            var = fmaxf(var, 0.0f);
            float std_ = sqrtf(var);
            float iq   = 1.0f - 2.0f * fabsf(mean - 0.5f);
            s_qual[bb] = (std_ + iq + var) * (1.0f / 3.0f);
            s_mean[bb] = mean;
        }
    }
    __syncthreads();

    // ---- Phase 3: batch reduce + code (thread 0) ----
    if (t == 0) {
        float q = 0.f, m = 0.f;
#pragma unroll
        for (int b = 0; b < NB; ++b) { q += s_qual[b]; m += s_mean[b]; }
        q *= (1.0f / NB);
        m *= (1.0f / NB);

        bool low    = q < 0.7f;
        bool strong = low  && (r_strong[p] < 0.8f);
        bool drop   = low  && (q < 0.3f) && (r_drop[p] < 0.1f);
        bool els    = !low && (r_else[p] < 0.3f);

        int code = 0;
        if (strong) code = aug_choice[p] + 1;      // 1..4
        if (els)    code = slight_choice[p] + 5;   // 5..6
        if (drop)   code = 7;

        float scale = 0.f;
        if      (code == 1) scale = 0.1f;
        else if (code == 3) scale = bright_f[p];
        else if (code == 4) scale = contrast_f[p];
        else if (code == 5) scale = 0.05f;
        else if (code == 6) scale = slight_f[p];

        s_code  = code;
        s_scale = scale;
        s_mpp   = m;
    }
    __syncthreads();

    const int   code  = s_code;               // uniform across CTA
    const float scale = s_scale;
    const float mpp   = s_mpp;

    // ---- Phase 4: apply + store (fully coalesced, same pattern as load) ----
    if (code == 0) {
#pragma unroll
        for (int b = 0; b < NB; ++b)
            __stcs(&out[pbase + (size_t)b * IMGSZ], v[b]);
    } else if (code == 7) {
#pragma unroll
        for (int b = 0; b < NB; ++b)
            __stcs(&out[pbase + (size_t)b * IMGSZ], 0.0f);
    } else if (code == 2) {
        // 3x3 zero-padded blur confined to the patch, from the smem tile.
#pragma unroll 4
        for (int b = 0; b < NB; ++b) {
            const float* tb = tile + b * TBATCH;
            float sum = 0.f;
#pragma unroll
            for (int dy = -1; dy <= 1; ++dy) {
                const int rr = r + dy;
                if (rr < 0 || rr >= PS) continue;
#pragma unroll
                for (int dx = -1; dx <= 1; ++dx) {
                    const int cc = c + dx;
                    if (cc < 0 || cc >= PS) continue;
                    sum += tb[rr * TROW + cc];
                }
            }
            __stcs(&out[pbase + (size_t)b * IMGSZ], sum * (1.0f / 9.0f));
        }
    } else if (code == 1 || code == 5) {
        // chunk the noise loads (MLP=8) to bound register pressure
#pragma unroll
        for (int b0 = 0; b0 < NB; b0 += 8) {
            float n[8];
#pragma unroll
            for (int k = 0; k < 8; ++k)
                n[k] = noise[pbase + (size_t)(b0 + k) * IMGSZ];
#pragma unroll
            for (int k = 0; k < 8; ++k)
                __stcs(&out[pbase + (size_t)(b0 + k) * IMGSZ],
                       clamp01(fmaf(n[k], scale, v[b0 + k])));
        }
    } else if (code == 3 || code == 6) {
#pragma unroll
        for (int b = 0; b < NB; ++b)
            __stcs(&out[pbase + (size_t)b * IMGSZ], clamp01(v[b] * scale));
    } else { // code == 4 (contrast)
#pragma unroll
        for (int b = 0; b < NB; ++b)
            __stcs(&out[pbase + (size_t)b * IMGSZ],
                   clamp01(fmaf(v[b] - mpp, scale, mpp)));
    }
}

extern "C" void kernel_launch(void* const* d_in, const int* in_sizes, int n_in,
                              void* d_out, int out_size) {
    const float* img           = (const float*)d_in[0];
    const float* noise         = (const float*)d_in[1];
    const float* r_strong      = (const float*)d_in[2];
    const float* r_drop        = (const float*)d_in[3];
    const float* r_else        = (const float*)d_in[4];
    const float* bright_f      = (const float*)d_in[5];
    const float* contrast_f    = (const float*)d_in[6];
    const float* slight_f      = (const float*)d_in[7];
    const int*   aug_choice    = (const int*)d_in[8];
    const int*   slight_choice = (const int*)d_in[9];
    float* out = (float*)d_out;

    fused_kernel<<<NPATCH, 256>>>(img, noise, r_strong, r_drop, r_else,
                                  bright_f, contrast_f, slight_f,
                                  aug_choice, slight_choice, out);
}